// round 9
// baseline (speedup 1.0000x reference)
#include <cuda_runtime.h>

#define NN 50000
#define EPSV 1.000001f
#define FULLMASK 0xffffffffu

// Scratch: xm rows for both convs (float4 layout: row n = 16 float4s), and
// attention scalars: [s_src_l | s_tgt_l | s_src_u | s_tgt_u], each NN floats.
__device__ float4 g_xm_l[NN * 16];
__device__ float4 g_xm_u[NN * 16];
__device__ float  g_s[4 * NN];

__device__ __forceinline__ void fma4(float4& acc, float s, float4 wv) {
    acc.x = fmaf(s, wv.x, acc.x);
    acc.y = fmaf(s, wv.y, acc.y);
    acc.z = fmaf(s, wv.z, acc.z);
    acc.w = fmaf(s, wv.w, acc.w);
}

__device__ __forceinline__ float dot4(float4 a, float4 b) {
    return a.x * b.x + a.y * b.y + a.z * b.z + a.w * b.w;
}

// ---------------------------------------------------------------------------
// Node kernel: per node n compute xm_l = x@w_l, xm_u = x@w_u, wx = x@w_lin*EPS,
// plus s_src/s_tgt attention scalars for both convs.
// 16 threads per node group, 4 nodes per group, 8 groups per 128-thread block.
// Weights live in 48KB static shared (3 x 64x64 fp32).
// ---------------------------------------------------------------------------
__global__ void __launch_bounds__(128)
node_kernel(const float4* __restrict__ x4,
            const float4* __restrict__ wl4g,
            const float*  __restrict__ al,
            const float4* __restrict__ wu4g,
            const float*  __restrict__ au,
            const float4* __restrict__ ww4g,
            float4* __restrict__ out4)
{
    __shared__ float4 s_wl[1024];
    __shared__ float4 s_wu[1024];
    __shared__ float4 s_ww[1024];

    int tid = threadIdx.x;
    for (int k = tid; k < 1024; k += 128) {
        s_wl[k] = wl4g[k];
        s_wu[k] = wu4g[k];
        s_ww[k] = ww4g[k];
    }
    __syncthreads();

    int lane = tid & 15;
    int grp  = tid >> 4;
    int base = (blockIdx.x * 8 + grp) * 4;   // first of 4 nodes for this group

    const float4* al4 = (const float4*)al;
    const float4* au4 = (const float4*)au;
    float4 a_ls = al4[lane];        // a_lower[:64]   (src part)
    float4 a_lt = al4[16 + lane];   // a_lower[64:]   (tgt part)
    float4 a_us = au4[lane];
    float4 a_ut = au4[16 + lane];

    float4 xv[4];
    #pragma unroll
    for (int r = 0; r < 4; ++r) {
        int n = base + r;
        xv[r] = (n < NN) ? x4[n * 16 + lane] : make_float4(0.f, 0.f, 0.f, 0.f);
    }

    float4 accl[4], accu[4], accw[4];
    #pragma unroll
    for (int r = 0; r < 4; ++r) {
        accl[r] = make_float4(0.f, 0.f, 0.f, 0.f);
        accu[r] = make_float4(0.f, 0.f, 0.f, 0.f);
        accw[r] = make_float4(0.f, 0.f, 0.f, 0.f);
    }

    #pragma unroll 4
    for (int c4 = 0; c4 < 16; ++c4) {
        float b[4][4];
        #pragma unroll
        for (int r = 0; r < 4; ++r) {
            b[0][r] = __shfl_sync(FULLMASK, xv[r].x, c4, 16);
            b[1][r] = __shfl_sync(FULLMASK, xv[r].y, c4, 16);
            b[2][r] = __shfl_sync(FULLMASK, xv[r].z, c4, 16);
            b[3][r] = __shfl_sync(FULLMASK, xv[r].w, c4, 16);
        }
        #pragma unroll
        for (int k = 0; k < 4; ++k) {
            int c = c4 * 4 + k;
            float4 wlc = s_wl[c * 16 + lane];
            float4 wuc = s_wu[c * 16 + lane];
            float4 wwc = s_ww[c * 16 + lane];
            #pragma unroll
            for (int r = 0; r < 4; ++r) {
                float xc = b[k][r];
                fma4(accl[r], xc, wlc);
                fma4(accu[r], xc, wuc);
                fma4(accw[r], xc, wwc);
            }
        }
    }

    #pragma unroll
    for (int r = 0; r < 4; ++r) {
        int n = base + r;
        bool valid = (n < NN);
        int off = n * 16 + lane;
        if (valid) {
            g_xm_l[off] = accl[r];
            g_xm_u[off] = accu[r];
            float4 wv = accw[r];
            out4[off] = make_float4(wv.x * EPSV, wv.y * EPSV, wv.z * EPSV, wv.w * EPSV);
        }
        // attention scalars: dot over all 64 channels, reduce across 16 lanes
        float sl_s = dot4(accl[r], a_ls);
        float sl_t = dot4(accl[r], a_lt);
        float su_s = dot4(accu[r], a_us);
        float su_t = dot4(accu[r], a_ut);
        #pragma unroll
        for (int m = 8; m >= 1; m >>= 1) {
            sl_s += __shfl_xor_sync(FULLMASK, sl_s, m, 16);
            sl_t += __shfl_xor_sync(FULLMASK, sl_t, m, 16);
            su_s += __shfl_xor_sync(FULLMASK, su_s, m, 16);
            su_t += __shfl_xor_sync(FULLMASK, su_t, m, 16);
        }
        if (valid && lane == 0) {
            g_s[n]          = sl_s;
            g_s[NN + n]     = sl_t;
            g_s[2 * NN + n] = su_s;
            g_s[3 * NN + n] = su_t;
        }
    }
}

// ---------------------------------------------------------------------------
// Edge kernel: one 16-thread group per edge slot; slots [0,E) = lower conv,
// [E,2E) = upper conv. Indices are int32 (JAX x64 disabled => int64 request
// silently yields int32), layout [2, E] row-major: ind[e] = target i,
// ind[E+e] = source j. Lane 0 computes alpha = elu(s_src[j]+s_tgt[i])*val,
// broadcasts via width-16 shuffle; all 16 lanes gather a float4 of xm[j] and
// issue red.global.add.v4.f32 into out[i] (fully coalesced 256B per edge).
// ---------------------------------------------------------------------------
__global__ void __launch_bounds__(256)
edge_kernel(const int*   __restrict__ li,
            const float* __restrict__ lv,
            const int*   __restrict__ ui,
            const float* __restrict__ uv,
            float* __restrict__ out, int E)
{
    unsigned t    = blockIdx.x * 256u + threadIdx.x;
    unsigned slot = t >> 4;
    int lane      = (int)(t & 15u);
    bool valid    = slot < 2u * (unsigned)E;

    bool up = valid && (slot >= (unsigned)E);
    unsigned e = up ? (slot - (unsigned)E) : slot;
    if (!valid) e = 0;

    const int*    ind  = up ? ui : li;
    const float*  val  = up ? uv : lv;
    const float*  ssrc = up ? (g_s + 2 * NN) : g_s;
    const float*  stgt = up ? (g_s + 3 * NN) : (g_s + NN);
    const float4* xm   = up ? g_xm_u : g_xm_l;

    int i = 0, j = 0;
    float alpha = 0.f;
    if (valid && lane == 0) {
        i = ind[e];
        j = ind[E + e];
        float a  = ssrc[j] + stgt[i];
        float ev = (a > 0.f) ? a : (__expf(a) - 1.f);
        alpha = ev * val[e];
    }
    // all warp lanes converged here (no early returns) -> full-mask shuffles ok
    i     = __shfl_sync(FULLMASK, i, 0, 16);
    j     = __shfl_sync(FULLMASK, j, 0, 16);
    alpha = __shfl_sync(FULLMASK, alpha, 0, 16);

    if (valid) {
        float4 m = xm[j * 16 + lane];
        float* dst = out + i * 64 + lane * 4;
        asm volatile("red.global.add.v4.f32 [%0], {%1, %2, %3, %4};"
                     :: "l"(dst),
                        "f"(m.x * alpha), "f"(m.y * alpha),
                        "f"(m.z * alpha), "f"(m.w * alpha)
                     : "memory");
    }
}

// ---------------------------------------------------------------------------
// In-place ReLU epilogue.
// ---------------------------------------------------------------------------
__global__ void __launch_bounds__(256)
relu_kernel(float4* __restrict__ out4, int n4)
{
    int idx = blockIdx.x * 256 + threadIdx.x;
    if (idx < n4) {
        float4 v = out4[idx];
        v.x = fmaxf(v.x, 0.f);
        v.y = fmaxf(v.y, 0.f);
        v.z = fmaxf(v.z, 0.f);
        v.w = fmaxf(v.w, 0.f);
        out4[idx] = v;
    }
}

extern "C" void kernel_launch(void* const* d_in, const int* in_sizes, int n_in,
                              void* d_out, int out_size)
{
    const float* x  = (const float*)d_in[0];
    const int*   li = (const int*)d_in[1];
    const float* lv = (const float*)d_in[2];
    const int*   ui = (const int*)d_in[3];
    const float* uv = (const float*)d_in[4];
    const float* wl = (const float*)d_in[5];
    const float* al = (const float*)d_in[6];
    const float* wu = (const float*)d_in[7];
    const float* au = (const float*)d_in[8];
    const float* ww = (const float*)d_in[9];
    float* out = (float*)d_out;

    int E = in_sizes[2];   // element count of lower_values

    // Node kernel: 32 nodes per block (8 groups x 4 nodes)
    int node_blocks = (NN + 31) / 32;
    node_kernel<<<node_blocks, 128>>>((const float4*)x,
                                      (const float4*)wl, al,
                                      (const float4*)wu, au,
                                      (const float4*)ww,
                                      (float4*)out);

    // Edge kernel: 16 threads per edge slot, 2E slots
    long long total_threads = 2LL * E * 16;
    int edge_blocks = (int)((total_threads + 255) / 256);
    edge_kernel<<<edge_blocks, 256>>>(li, lv, ui, uv, out, E);

    // ReLU epilogue
    int n4 = NN * 16;
    relu_kernel<<<(n4 + 255) / 256, 256>>>((float4*)out, n4);
}

// round 12
// speedup vs baseline: 1.3013x; 1.3013x over previous
#include <cuda_runtime.h>

#define NN 50000
#define EPSV 1.000001f
#define FULLMASK 0xffffffffu
#define CAP 112   // max combined (lower+upper) degree per target; Poisson(32) tail ~0

// Scratch (device globals; no allocation allowed):
__device__ float4 g_xm_l[NN * 16];   // x @ w_lower         (12.8 MB)
__device__ float4 g_xm_u[NN * 16];   // x @ w_upper         (12.8 MB)
__device__ float4 g_wx[NN * 16];     // (x @ w_lin) * EPS   (12.8 MB)
__device__ float  g_s[4 * NN];       // [s_src_l | s_tgt_l | s_src_u | s_tgt_u]
__device__ int    g_cnt[NN];         // per-target record count
__device__ int2   g_rec[NN * CAP];   // per-target edge records: (.x=(j<<1)|up, .y=alpha bits)

__device__ __forceinline__ void fma4(float4& acc, float s, float4 wv) {
    acc.x = fmaf(s, wv.x, acc.x);
    acc.y = fmaf(s, wv.y, acc.y);
    acc.z = fmaf(s, wv.z, acc.z);
    acc.w = fmaf(s, wv.w, acc.w);
}

__device__ __forceinline__ float dot4(float4 a, float4 b) {
    return a.x * b.x + a.y * b.y + a.z * b.z + a.w * b.w;
}

// ---------------------------------------------------------------------------
// Node kernel: per node n compute xm_l = x@w_l, xm_u = x@w_u, wx = x@w_lin*EPS,
// plus s_src/s_tgt attention scalars for both convs. Also zeroes g_cnt.
// 16 threads per node group, 4 nodes per group, 8 groups per 128-thread block.
// ---------------------------------------------------------------------------
__global__ void __launch_bounds__(128)
node_kernel(const float4* __restrict__ x4,
            const float4* __restrict__ wl4g,
            const float*  __restrict__ al,
            const float4* __restrict__ wu4g,
            const float*  __restrict__ au,
            const float4* __restrict__ ww4g)
{
    __shared__ float4 s_wl[1024];
    __shared__ float4 s_wu[1024];
    __shared__ float4 s_ww[1024];

    int tid = threadIdx.x;
    // zero the bin counters for this replay (fill_kernel runs after we finish)
    int gt = blockIdx.x * 128 + tid;
    if (gt < NN) g_cnt[gt] = 0;

    for (int k = tid; k < 1024; k += 128) {
        s_wl[k] = wl4g[k];
        s_wu[k] = wu4g[k];
        s_ww[k] = ww4g[k];
    }
    __syncthreads();

    int lane = tid & 15;
    int grp  = tid >> 4;
    int base = (blockIdx.x * 8 + grp) * 4;

    const float4* al4 = (const float4*)al;
    const float4* au4 = (const float4*)au;
    float4 a_ls = al4[lane];
    float4 a_lt = al4[16 + lane];
    float4 a_us = au4[lane];
    float4 a_ut = au4[16 + lane];

    float4 xv[4];
    #pragma unroll
    for (int r = 0; r < 4; ++r) {
        int n = base + r;
        xv[r] = (n < NN) ? x4[n * 16 + lane] : make_float4(0.f, 0.f, 0.f, 0.f);
    }

    float4 accl[4], accu[4], accw[4];
    #pragma unroll
    for (int r = 0; r < 4; ++r) {
        accl[r] = make_float4(0.f, 0.f, 0.f, 0.f);
        accu[r] = make_float4(0.f, 0.f, 0.f, 0.f);
        accw[r] = make_float4(0.f, 0.f, 0.f, 0.f);
    }

    #pragma unroll 4
    for (int c4 = 0; c4 < 16; ++c4) {
        float b[4][4];
        #pragma unroll
        for (int r = 0; r < 4; ++r) {
            b[0][r] = __shfl_sync(FULLMASK, xv[r].x, c4, 16);
            b[1][r] = __shfl_sync(FULLMASK, xv[r].y, c4, 16);
            b[2][r] = __shfl_sync(FULLMASK, xv[r].z, c4, 16);
            b[3][r] = __shfl_sync(FULLMASK, xv[r].w, c4, 16);
        }
        #pragma unroll
        for (int k = 0; k < 4; ++k) {
            int c = c4 * 4 + k;
            float4 wlc = s_wl[c * 16 + lane];
            float4 wuc = s_wu[c * 16 + lane];
            float4 wwc = s_ww[c * 16 + lane];
            #pragma unroll
            for (int r = 0; r < 4; ++r) {
                float xc = b[k][r];
                fma4(accl[r], xc, wlc);
                fma4(accu[r], xc, wuc);
                fma4(accw[r], xc, wwc);
            }
        }
    }

    #pragma unroll
    for (int r = 0; r < 4; ++r) {
        int n = base + r;
        bool valid = (n < NN);
        int off = n * 16 + lane;
        if (valid) {
            g_xm_l[off] = accl[r];
            g_xm_u[off] = accu[r];
            float4 wv = accw[r];
            g_wx[off] = make_float4(wv.x * EPSV, wv.y * EPSV, wv.z * EPSV, wv.w * EPSV);
        }
        float sl_s = dot4(accl[r], a_ls);
        float sl_t = dot4(accl[r], a_lt);
        float su_s = dot4(accu[r], a_us);
        float su_t = dot4(accu[r], a_ut);
        #pragma unroll
        for (int m = 8; m >= 1; m >>= 1) {
            sl_s += __shfl_xor_sync(FULLMASK, sl_s, m, 16);
            sl_t += __shfl_xor_sync(FULLMASK, sl_t, m, 16);
            su_s += __shfl_xor_sync(FULLMASK, su_s, m, 16);
            su_t += __shfl_xor_sync(FULLMASK, su_t, m, 16);
        }
        if (valid && lane == 0) {
            g_s[n]          = sl_s;
            g_s[NN + n]     = sl_t;
            g_s[2 * NN + n] = su_s;
            g_s[3 * NN + n] = su_t;
        }
    }
}

// ---------------------------------------------------------------------------
// Fill kernel: 1 thread per edge slot ([0,E)=lower, [E,2E)=upper).
// Computes alpha and appends (j, conv, alpha) record to target i's bin.
// Overflow (never in practice): atomically folds the message into g_wx
// (pre-relu accumulator), which the gather kernel reads afterwards.
// ---------------------------------------------------------------------------
__global__ void __launch_bounds__(256)
fill_kernel(const int*   __restrict__ li,
            const float* __restrict__ lv,
            const int*   __restrict__ ui,
            const float* __restrict__ uv,
            int E)
{
    int t = blockIdx.x * 256 + threadIdx.x;
    if (t >= 2 * E) return;
    bool up = (t >= E);
    int e = up ? (t - E) : t;

    const int*   ind  = up ? ui : li;
    const float* val  = up ? uv : lv;
    const float* ssrc = up ? (g_s + 2 * NN) : g_s;
    const float* stgt = up ? (g_s + 3 * NN) : (g_s + NN);

    int i = ind[e];          // target
    int j = ind[E + e];      // source
    float a  = ssrc[j] + stgt[i];
    float ev = (a > 0.f) ? a : (__expf(a) - 1.f);
    float alpha = ev * val[e];

    int pos = atomicAdd(&g_cnt[i], 1);
    if (pos < CAP) {
        g_rec[i * CAP + pos] = make_int2((j << 1) | (up ? 1 : 0), __float_as_int(alpha));
    } else {
        // correctness-safe fallback (probability ~0 for Poisson(32) vs CAP=112)
        const float* xm = (const float*)(up ? g_xm_u : g_xm_l) + (size_t)j * 64;
        float* dst = (float*)g_wx + (size_t)i * 64;
        for (int c = 0; c < 64; ++c)
            atomicAdd(dst + c, alpha * xm[c]);
    }
}

// ---------------------------------------------------------------------------
// Gather kernel: 16 threads per target node, 16 targets per 256-thread block.
// Reads records coalesced in chunks of 16, shuffle-broadcasts (j, alpha),
// accumulates alpha*xm[j] in registers, adds wx, applies ReLU, one 256B store.
// NOTE: the two 16-lane halves of a warp diverge (different cnt), so shuffles
// use the half-warp member mask.
// ---------------------------------------------------------------------------
__global__ void __launch_bounds__(256)
gather_kernel(float4* __restrict__ out4)
{
    int tid  = threadIdx.x;
    int lane = tid & 15;
    int i    = blockIdx.x * 16 + (tid >> 4);
    if (i >= NN) return;

    unsigned hmask = 0xFFFFu << (threadIdx.x & 16);  // this 16-group's warp lanes

    int cnt = g_cnt[i];
    int cl  = cnt < CAP ? cnt : CAP;

    float4 acc = g_wx[i * 16 + lane];

    const int2* bin = g_rec + (size_t)i * CAP;
    for (int base = 0; base < cl; base += 16) {
        int rem = cl - base;
        int m   = rem < 16 ? rem : 16;
        int2 r = make_int2(0, 0);
        if (lane < m) r = bin[base + lane];
        #pragma unroll 4
        for (int k = 0; k < m; ++k) {
            int   jj = __shfl_sync(hmask, r.x, k, 16);
            float av = __shfl_sync(hmask, __int_as_float(r.y), k, 16);
            const float4* xm = (jj & 1) ? g_xm_u : g_xm_l;
            float4 v = xm[(jj >> 1) * 16 + lane];
            fma4(acc, av, v);
        }
    }

    acc.x = fmaxf(acc.x, 0.f);
    acc.y = fmaxf(acc.y, 0.f);
    acc.z = fmaxf(acc.z, 0.f);
    acc.w = fmaxf(acc.w, 0.f);
    out4[i * 16 + lane] = acc;
}

extern "C" void kernel_launch(void* const* d_in, const int* in_sizes, int n_in,
                              void* d_out, int out_size)
{
    const float* x  = (const float*)d_in[0];
    const int*   li = (const int*)d_in[1];
    const float* lv = (const float*)d_in[2];
    const int*   ui = (const int*)d_in[3];
    const float* uv = (const float*)d_in[4];
    const float* wl = (const float*)d_in[5];
    const float* al = (const float*)d_in[6];
    const float* wu = (const float*)d_in[7];
    const float* au = (const float*)d_in[8];
    const float* ww = (const float*)d_in[9];
    float* out = (float*)d_out;

    int E = in_sizes[2];   // element count of lower_values

    // 1) Fused node GEMMs + attention scalars (+ counter zeroing)
    int node_blocks = (NN + 31) / 32;
    node_kernel<<<node_blocks, 128>>>((const float4*)x,
                                      (const float4*)wl, al,
                                      (const float4*)wu, au,
                                      (const float4*)ww);

    // 2) Edge binning (1 thread per edge slot, both convs)
    int fill_blocks = (2 * E + 255) / 256;
    fill_kernel<<<fill_blocks, 256>>>(li, lv, ui, uv, E);

    // 3) Per-target gather + wx + ReLU (final output)
    int gather_blocks = (NN + 15) / 16;
    gather_kernel<<<gather_blocks, 256>>>((float4*)out);
}